// round 13
// baseline (speedup 1.0000x reference)
#include <cuda_runtime.h>
#include <cuda_bf16.h>
#include <cstdint>

// ============================================================================
// HospitalStaffingModel via warp-level FP8 mma.sync (m16n8k32 e4m3) on sm_103.
// Round 13: end-to-end e4m3 (A, B, h1, h2, a3) to halve L1TEX bytes (the
// binding pipe) and halve MMA instruction count. Shell: 64 rows/CTA, 256 thr
// (8 N-warps, MT=4), 2 CTAs/SM, pair-interleaved LDG.128 B images.
// Epilogues remain exact fp32 (BN fold, biases, range masks, output stores).
// ============================================================================

typedef unsigned long long ull;
#define B_TOTAL 131072
#define EPSV    1e-5f
#define NEGV    -1e9f

// ---- prepacked FP8 weight fragment buffer (ull entries, pair-interleaved) ---
// fragment (ks,nt), lane l: b0 = W[k0+tg*4 .. +3][n], b1 = W[k0+16+tg*4 ..][n]
// with tg=l&3, n=nt*8+(l>>2), k0=ks*32. ull = b0 | b1<<32.
// pair layout: ull offset = base + ((ks*NPW + nt/2)*32 + lane)*2 + (nt&1)
#define GW0 0u        // W0: 2 ks x 32 np  -> 4096 ull
#define GW1 4096u     // W1: 16 ks x 16 np -> 16384
#define GWH 20480u    // [nW1|dW1]: 8 ks x 8 np -> 4096
#define GWF 24576u    // blockdiag(nW2,dW2): 2 ks x 16 np -> 2048
#define GTOT 26624u

__device__ __align__(1024) ull g_wfrag[GTOT];

// ---- SMEM layout (byte offsets); activations are e4m3 bytes ------------------
// strides: 16B-odd-multiple pad -> conflict-free ldmatrix
#define SO_CS    0        // 1920 f32 consts (7680 B)
#define SO_SN    7680     // 64 int
#define SO_SD    7936     // 64 int
#define SO_XH    8192     // region A: xs [64][80B] (L0) / h2 [64][272B] (17408 B)
#define SO_H1    25600    // h1 [64][528B] (33792 B); a3 [64][144B] overlays after L1
#define SMEM_BYTES 59392

// ---- helpers -----------------------------------------------------------------
__device__ __forceinline__ uint32_t smem_u32(const void* p) {
    uint32_t a;
    asm("{ .reg .u64 t; cvta.to.shared.u64 t, %1; cvt.u32.u64 %0, t; }" : "=r"(a) : "l"(p));
    return a;
}
// e4m3x2 pack: byte0 = lo, byte1 = hi (first PTX src is the HIGH byte)
__device__ __forceinline__ unsigned short pack_e4m3x2(float lo, float hi) {
    unsigned short r;
    asm("cvt.rn.satfinite.e4m3x2.f32 %0, %1, %2;" : "=h"(r) : "f"(hi), "f"(lo));
    return r;
}
__device__ __forceinline__ uint32_t pack4_e4m3(float f0, float f1, float f2, float f3) {
    const uint32_t lo = pack_e4m3x2(f0, f1);
    const uint32_t hi = pack_e4m3x2(f2, f3);
    return lo | (hi << 16);
}
__device__ __forceinline__ void mma16832(float* c, const uint32_t* a, uint32_t b0, uint32_t b1) {
    asm volatile(
        "mma.sync.aligned.m16n8k32.row.col.f32.e4m3.e4m3.f32 "
        "{%0,%1,%2,%3}, {%4,%5,%6,%7}, {%8,%9}, {%0,%1,%2,%3};"
        : "+f"(c[0]), "+f"(c[1]), "+f"(c[2]), "+f"(c[3])
        : "r"(a[0]), "r"(a[1]), "r"(a[2]), "r"(a[3]), "r"(b0), "r"(b1));
}
__device__ __forceinline__ void ldsm_x4(uint32_t* r, uint32_t saddr) {
    asm volatile("ldmatrix.sync.aligned.m8n8.x4.shared.b16 {%0,%1,%2,%3}, [%4];"
                 : "=r"(r[0]), "=r"(r[1]), "=r"(r[2]), "=r"(r[3]) : "r"(saddr));
}

// Register-tiled FP8 block: C[MT][NT][4] += A[rows 0..16*MT) x Wfrag, K=KS*32.
// A via 2-buffer JIT ldmatrix.x4 (byte-layout identical to bf16 case, 4 fp8/reg);
// B via LDG.128 pair fetches, PF-deep register ring. All strides in BYTES.
template<int KS, int NT, int MT>
__device__ __forceinline__ void gemm_block(
    uint32_t act_b, int SAB, int kpb,
    const uint4* __restrict__ wf, int NPW, int npb,
    int lane, float* C)
{
    constexpr int NP = NT / 2;
    constexpr int PF = (KS < 3) ? KS : 3;
    const int quad  = lane >> 3;
    const int lrow  = (quad & 1) * 8 + (lane & 7);
    const int khalf = quad >> 1;
    const uint4* __restrict__ wfl = wf + (size_t)npb * 32 + lane;

    uint32_t abase[MT];
    #pragma unroll
    for (int mt = 0; mt < MT; mt++)
        abase[mt] = act_b + (uint32_t)((mt * 16 + lrow) * SAB + kpb + khalf * 16);

    uint4 b[PF][NP];
    #pragma unroll
    for (int s = 0; s < PF - 1; s++)
        #pragma unroll
        for (int np = 0; np < NP; np++)
            b[s][np] = wfl[((size_t)s * NPW + np) * 32];

    uint32_t a[2][4];
    ldsm_x4(a[0], abase[0]);                     // ks=0, mt=0

    #pragma unroll
    for (int ks = 0; ks < KS; ks++) {
        if (ks + PF - 1 < KS) {
            #pragma unroll
            for (int np = 0; np < NP; np++)
                b[(ks + PF - 1) % PF][np] = wfl[((size_t)(ks + PF - 1) * NPW + np) * 32];
        }
        #pragma unroll
        for (int mt = 0; mt < MT; mt++) {
            const int cur = (ks * MT + mt) & 1;
            if (mt + 1 < MT)
                ldsm_x4(a[cur ^ 1], abase[mt + 1] + ks * 32);
            else if (ks + 1 < KS)
                ldsm_x4(a[cur ^ 1], abase[0] + (ks + 1) * 32);
            const uint4* bb = b[ks % PF];
            #pragma unroll
            for (int np = 0; np < NP; np++) {
                mma16832(C + (mt * NT + np * 2) * 4,     a[cur], bb[np].x, bb[np].y);
                mma16832(C + (mt * NT + np * 2 + 1) * 4, a[cur], bb[np].z, bb[np].w);
            }
        }
    }
}

// ============================================================================
// Prepack: bake e4m3 B-fragment images, pair-interleaved.
// ============================================================================
__global__ void hosp_prepack(const float* __restrict__ W0, const float* __restrict__ W1,
                             const float* __restrict__ nW1, const float* __restrict__ dW1,
                             const float* __restrict__ nW2, const float* __restrict__ dW2)
{
    const int idx = blockIdx.x * 256 + threadIdx.x;
    if (idx >= (int)GTOT) return;

    int base, NPW, region;
    if      (idx < 4096)  { base = 0;     NPW = 32; region = 0; }
    else if (idx < 20480) { base = 4096;  NPW = 16; region = 1; }
    else if (idx < 24576) { base = 20480; NPW = 8;  region = 2; }
    else                  { base = 24576; NPW = 16; region = 3; }

    const int e    = idx - base;
    const int half = e & 1;
    const int e2   = e >> 1;
    const int lane = e2 & 31;
    const int gi   = e2 >> 5;
    const int np   = gi % NPW;
    const int ks   = gi / NPW;
    const int nt   = np * 2 + half;
    const int tg   = lane & 3, gg = lane >> 2;
    const int k0   = ks * 32 + tg * 4;

    const float* W; int stride, n;
    if (region == 0)      { W = W0; stride = 512; n = nt * 8 + gg; }
    else if (region == 1) { W = W1; stride = 256; n = nt * 8 + gg; }
    else if (region == 2) {
        const int ng = nt * 8 + gg;
        W = (ng < 64) ? nW1 : dW1; stride = 64; n = ng & 63;
    } else {
        W = (nt < 16) ? nW2 : dW2; stride = 128; n = (nt & 15) * 8 + gg;
    }

    float f[8];
    #pragma unroll
    for (int i = 0; i < 4; i++) {
        f[i]     = W[(size_t)(k0 + i)      * stride + n];
        f[4 + i] = W[(size_t)(k0 + 16 + i) * stride + n];
    }
    const uint32_t b0 = pack4_e4m3(f[0], f[1], f[2], f[3]);
    const uint32_t b1 = pack4_e4m3(f[4], f[5], f[6], f[7]);
    g_wfrag[idx] = (ull)b0 | ((ull)b1 << 32);
}

// ============================================================================
// Main kernel: 64 rows/CTA, 256 threads (8 N-warps, MT=4). 2 CTAs/SM. FP8.
// ============================================================================
__global__ __launch_bounds__(256, 2)
void hosp_fp8_kernel(
    const float* __restrict__ x,
    const float* __restrict__ b0,  const float* __restrict__ g0,
    const float* __restrict__ be0, const float* __restrict__ rm0, const float* __restrict__ rv0,
    const float* __restrict__ b1,  const float* __restrict__ g1,
    const float* __restrict__ be1, const float* __restrict__ rm1, const float* __restrict__ rv1,
    const float* __restrict__ nb1, const float* __restrict__ nb2,
    const float* __restrict__ db1, const float* __restrict__ db2,
    float* __restrict__ out)
{
    extern __shared__ unsigned char smem[];
    float* cs  = reinterpret_cast<float*>(smem + SO_CS);
    int*   sns = reinterpret_cast<int*>(smem + SO_SN);
    int*   sds = reinterpret_cast<int*>(smem + SO_SD);
    unsigned char* xh_p = smem + SO_XH;     // xs (L0) then h2
    unsigned char* h1_p = smem + SO_H1;     // h1 then a3

    const uint32_t xh_b = smem_u32(xh_p);
    const uint32_t h1_b = smem_u32(h1_p);
    const uint4* wf4 = reinterpret_cast<const uint4*>(g_wfrag);

    const int tid  = threadIdx.x;
    const int lane = tid & 31;
    const int nw   = tid >> 5;         // N-warp (0..7)
    const int g    = lane >> 2, t = lane & 3;
    const int r0   = blockIdx.x * 64;

    // ---- fold BN consts + biases --------------------------------------------
    for (int i = tid; i < 512; i += 256) {
        const float s = g0[i] * rsqrtf(rv0[i] + EPSV);
        cs[i] = s; cs[512 + i] = (b0[i] - rm0[i]) * s + be0[i];
    }
    {
        const int i = tid;
        const float s = g1[i] * rsqrtf(rv1[i] + EPSV);
        cs[1024 + i] = s; cs[1280 + i] = (b1[i] - rm1[i]) * s + be1[i];
    }
    if (tid < 64) { cs[1536 + tid] = nb1[tid]; cs[1600 + tid] = db1[tid]; }
    if (tid < 128) { cs[1664 + tid] = nb2[tid]; cs[1792 + tid] = db2[tid]; }

    // ---- x tile: fp32 -> e4m3, [64 rows][80B] + mask thresholds --------------
    {
        const float4* x4 = reinterpret_cast<const float4*>(x + (size_t)r0 * 64);
        for (int i = tid; i < 1024; i += 256) {
            const int row = i >> 4, kq = i & 15;
            const float4 v = x4[row * 16 + kq];
            *reinterpret_cast<uint32_t*>(xh_p + row * 80 + kq * 4) =
                pack4_e4m3(v.x, v.y, v.z, v.w);
        }
        if (tid < 64)       sns[tid] = (int)x[(size_t)(r0 + tid) * 64 + 60];
        else if (tid < 128) sds[tid - 64] = (int)x[(size_t)(r0 + tid - 64) * 64 + 61];
    }
    __syncthreads();

    // ================= L0: K=64 (KS=2), two N-halves of 4 n-tiles each ========
    #pragma unroll 1
    for (int half = 0; half < 2; half++) {
        float C[64];
        #pragma unroll
        for (int i = 0; i < 64; i++) C[i] = 0.0f;
        const int ntb = nw * 8 + half * 4;
        gemm_block<2, 4, 4>(xh_b, 80, 0, wf4 + (GW0 >> 1), 32, ntb >> 1, lane, C);
        #pragma unroll
        for (int mt = 0; mt < 4; mt++)
            #pragma unroll
            for (int nt = 0; nt < 4; nt++) {
                const float* c = C + (mt * 4 + nt) * 4;
                const int j = (ntb + nt) * 8 + t * 2;
                const int rA = mt * 16 + g, rB = rA + 8;
                const float v0 = fmaxf(fmaf(c[0], cs[j],     cs[512 + j]),     0.0f);
                const float v1 = fmaxf(fmaf(c[1], cs[j + 1], cs[512 + j + 1]), 0.0f);
                const float v2 = fmaxf(fmaf(c[2], cs[j],     cs[512 + j]),     0.0f);
                const float v3 = fmaxf(fmaf(c[3], cs[j + 1], cs[512 + j + 1]), 0.0f);
                *reinterpret_cast<unsigned short*>(h1_p + rA * 528 + j) = pack_e4m3x2(v0, v1);
                *reinterpret_cast<unsigned short*>(h1_p + rB * 528 + j) = pack_e4m3x2(v2, v3);
            }
    }
    __syncthreads();   // h1 complete; xs dead

    // ================= L1: K=512 (KS=16) in one pipelined sweep ===============
    {
        float C[64];
        #pragma unroll
        for (int i = 0; i < 64; i++) C[i] = 0.0f;
        gemm_block<16, 4, 4>(h1_b, 528, 0, wf4 + (GW1 >> 1), 16, nw * 2, lane, C);
        #pragma unroll
        for (int mt = 0; mt < 4; mt++)
            #pragma unroll
            for (int nt = 0; nt < 4; nt++) {
                const float* c = C + (mt * 4 + nt) * 4;
                const int j = (nw * 4 + nt) * 8 + t * 2;
                const int rA = mt * 16 + g, rB = rA + 8;
                const float v0 = fmaxf(fmaf(c[0], cs[1024 + j],     cs[1280 + j]),     0.0f);
                const float v1 = fmaxf(fmaf(c[1], cs[1024 + j + 1], cs[1280 + j + 1]), 0.0f);
                const float v2 = fmaxf(fmaf(c[2], cs[1024 + j],     cs[1280 + j]),     0.0f);
                const float v3 = fmaxf(fmaf(c[3], cs[1024 + j + 1], cs[1280 + j + 1]), 0.0f);
                *reinterpret_cast<unsigned short*>(xh_p + rA * 272 + j) = pack_e4m3x2(v0, v1);
                *reinterpret_cast<unsigned short*>(xh_p + rB * 272 + j) = pack_e4m3x2(v2, v3);
            }
    }
    __syncthreads();   // h2 complete; h1 dead

    // ================= Heads: K=256 (KS=8), NT=2 -> a3 ========================
    {
        float C[32];
        #pragma unroll
        for (int i = 0; i < 32; i++) C[i] = 0.0f;
        gemm_block<8, 2, 4>(xh_b, 272, 0, wf4 + (GWH >> 1), 8, nw, lane, C);
        #pragma unroll
        for (int mt = 0; mt < 4; mt++)
            #pragma unroll
            for (int nt = 0; nt < 2; nt++) {
                const float* c = C + (mt * 2 + nt) * 4;
                const int j = (nw * 2 + nt) * 8 + t * 2;
                const int rA = mt * 16 + g, rB = rA + 8;
                const float v0 = fmaxf(c[0] + cs[1536 + j],     0.0f);
                const float v1 = fmaxf(c[1] + cs[1536 + j + 1], 0.0f);
                const float v2 = fmaxf(c[2] + cs[1536 + j],     0.0f);
                const float v3 = fmaxf(c[3] + cs[1536 + j + 1], 0.0f);
                *reinterpret_cast<unsigned short*>(h1_p + rA * 144 + j) = pack_e4m3x2(v0, v1);
                *reinterpret_cast<unsigned short*>(h1_p + rB * 144 + j) = pack_e4m3x2(v2, v3);
            }
    }
    __syncthreads();   // a3 complete; h2 dead

    // ================= Final: K=64 per head (KS=2) -> logits ==================
    {
        float C[64];
        #pragma unroll
        for (int i = 0; i < 64; i++) C[i] = 0.0f;
        const int ntb = nw * 4;                       // global nt 0..31
        const int kpb = (ntb >= 16) ? 64 : 0;         // doctor uses a3 bytes 64..127
        gemm_block<2, 4, 4>(h1_b, 144, kpb, wf4 + (GWF >> 1), 16, ntb >> 1, lane, C);

        const int head = (ntb >= 16) ? 1 : 0;
        const int* sm  = head ? sds : sns;
        float* ob = out + (head ? (size_t)B_TOTAL * 128 : 0) + (size_t)r0 * 128;

        #pragma unroll
        for (int mt = 0; mt < 4; mt++)
            #pragma unroll
            for (int nt = 0; nt < 4; nt++) {
                const float* c = C + (mt * 4 + nt) * 4;
                const int jg  = (ntb + nt) * 8 + t * 2;
                const int col = jg & 127;
                const int rA = mt * 16 + g, rB = rA + 8;
                const int smA = sm[rA], smB = sm[rB];
                const float bb0 = cs[1664 + jg], bb1 = cs[1664 + jg + 1];
                float2 vA, vB;
                vA.x = (col     <= smA) ? (c[0] + bb0) : NEGV;
                vA.y = (col + 1 <= smA) ? (c[1] + bb1) : NEGV;
                vB.x = (col     <= smB) ? (c[2] + bb0) : NEGV;
                vB.y = (col + 1 <= smB) ? (c[3] + bb1) : NEGV;
                *reinterpret_cast<float2*>(ob + (size_t)rA * 128 + col) = vA;
                *reinterpret_cast<float2*>(ob + (size_t)rB * 128 + col) = vB;
            }
    }
}

extern "C" void kernel_launch(void* const* d_in, const int* in_sizes, int n_in,
                              void* d_out, int out_size)
{
    const float* x   = (const float*)d_in[0];
    const float* W0  = (const float*)d_in[1];
    const float* b0  = (const float*)d_in[2];
    const float* g0  = (const float*)d_in[3];
    const float* be0 = (const float*)d_in[4];
    const float* rm0 = (const float*)d_in[5];
    const float* rv0 = (const float*)d_in[6];
    const float* W1  = (const float*)d_in[7];
    const float* b1  = (const float*)d_in[8];
    const float* g1  = (const float*)d_in[9];
    const float* be1 = (const float*)d_in[10];
    const float* rm1 = (const float*)d_in[11];
    const float* rv1 = (const float*)d_in[12];
    const float* nW1 = (const float*)d_in[13];
    const float* nb1 = (const float*)d_in[14];
    const float* nW2 = (const float*)d_in[15];
    const float* nb2 = (const float*)d_in[16];
    const float* dW1 = (const float*)d_in[17];
    const float* db1 = (const float*)d_in[18];
    const float* dW2 = (const float*)d_in[19];
    const float* db2 = (const float*)d_in[20];

    cudaFuncSetAttribute(hosp_fp8_kernel,
                         cudaFuncAttributeMaxDynamicSharedMemorySize, SMEM_BYTES);

    hosp_prepack<<<104, 256>>>(W0, W1, nW1, dW1, nW2, dW2);
    hosp_fp8_kernel<<<B_TOTAL / 64, 256, SMEM_BYTES>>>(
        x, b0, g0, be0, rm0, rv0, b1, g1, be1, rm1, rv1,
        nb1, nb2, db1, db2, (float*)d_out);
}